// round 13
// baseline (speedup 1.0000x reference)
#include <cuda_runtime.h>
#include <cuda_fp16.h>
#include <cstdint>

// ============================================================================
// LSTMCell for GB300 — sm_103 (non-'a') path: fp16 mma.sync + cp.async.bulk.
//
//   ONE main launch: bids 0..63 are pure CONVERTER CTAs (fp32->fp16 RN,
//   pre-tiled + SW128-swizzled, kc-major order, release-flag per chunk);
//   bids 64.. are GEMM CTAs (128x128xBK=64, 3-stage bulk-copy mbarrier ring,
//   trip-unrolled, round-robin producer that acquire-polls chunk flags),
//   fused fast-math float4 LSTM epilogue.
//   Conversion (~38us, DRAM-bound) hides under the tensor-bound mainloop.
// ============================================================================

#define DINLINE __device__ __forceinline__

__device__ __align__(1024) __half g_Ah[4096UL * 4096];   // 32 MB
__device__ __align__(1024) __half g_Bh[8192UL * 4096];   // 64 MB
__device__ int g_flags[8192];   // A: [mt*64+kc] (0..2047), B: 2048+[nt*64+kc]

// ------------------------------- helpers -----------------------------------
DINLINE uint32_t smem_u32(const void* p) {
    uint32_t a;
    asm("{ .reg .u64 t; cvta.to.shared.u64 t, %1; cvt.u32.u64 %0, t; }"
        : "=r"(a) : "l"(p));
    return a;
}

DINLINE void mbar_init(uint32_t a, uint32_t cnt) {
    asm volatile("mbarrier.init.shared.b64 [%0], %1;" :: "r"(a), "r"(cnt) : "memory");
}
DINLINE void mbar_expect(uint32_t a, uint32_t tx) {
    asm volatile("mbarrier.arrive.expect_tx.shared.b64 _, [%0], %1;"
                 :: "r"(a), "r"(tx) : "memory");
}
DINLINE void mbar_arrive(uint32_t a) {
    asm volatile("mbarrier.arrive.shared.b64 _, [%0];" :: "r"(a) : "memory");
}
DINLINE void mbar_wait(uint32_t mbar, uint32_t parity) {
    uint32_t done;
    asm volatile(
        "{\n .reg .pred p;\n"
        " mbarrier.try_wait.parity.acquire.cta.shared::cta.b64 p, [%1], %2;\n"
        " selp.b32 %0, 1, 0, p;\n}"
        : "=r"(done) : "r"(mbar), "r"(parity) : "memory");
    if (!done) {
        asm volatile(
            "{\n .reg .pred P1;\n"
            "WL%=:\n"
            " mbarrier.try_wait.parity.acquire.cta.shared::cta.b64 P1, [%0], %1, 0x989680;\n"
            " @P1 bra.uni WD%=;\n"
            " bra.uni WL%=;\n"
            "WD%=:\n}"
            :: "r"(mbar), "r"(parity) : "memory");
    }
}

DINLINE void bulk_g2s(uint32_t dst, const void* src, uint32_t bytes, uint32_t mbar) {
    asm volatile(
        "cp.async.bulk.shared::cluster.global.mbarrier::complete_tx::bytes [%0], [%1], %2, [%3];"
        :: "r"(dst), "l"(src), "r"(bytes), "r"(mbar) : "memory");
}

// fast-math gates (ex2/rcp approx; errors ~1e-7, negligible vs fp16 inputs)
DINLINE float ex2a(float x) { float y; asm("ex2.approx.f32 %0, %1;" : "=f"(y) : "f"(x)); return y; }
DINLINE float rcpa(float x) { float y; asm("rcp.approx.f32 %0, %1;" : "=f"(y) : "f"(x)); return y; }
DINLINE float sigf(float x)  { return rcpa(1.0f + ex2a(-1.442695041f * x)); }
DINLINE float tanhp(float x) { return 2.0f * sigf(2.0f * x) - 1.0f; }

// ------------------------ conversion + flag machinery -----------------------
// chunk id bits (within one operand buffer): [c:3][m:7][kc:6][tile:rest]
// dst byte = (t>>3)*128 + ((c ^ (m&7)) << 4)   (SW128 swizzle, 16B granules)
DINLINE void chunk_store(__half* dstbuf, uint32_t t,
                         const float4& v0, const float4& v1)
{
    __half2 h0 = __floats2half2_rn(v0.x, v0.y);
    __half2 h1 = __floats2half2_rn(v0.z, v0.w);
    __half2 h2 = __floats2half2_rn(v1.x, v1.y);
    __half2 h3 = __floats2half2_rn(v1.z, v1.w);
    uint4 out;
    out.x = *reinterpret_cast<uint32_t*>(&h0);
    out.y = *reinterpret_cast<uint32_t*>(&h1);
    out.z = *reinterpret_cast<uint32_t*>(&h2);
    out.w = *reinterpret_cast<uint32_t*>(&h3);
    const uint32_t c = t & 7u, m = (t >> 3) & 127u;
    *reinterpret_cast<uint4*>((unsigned char*)dstbuf +
        ((size_t)(t >> 3) << 7) + ((c ^ (m & 7u)) << 4)) = out;
}

DINLINE void poll_flag(const int* f) {
    int v;
    do {
        asm volatile("ld.acquire.gpu.global.u32 %0, [%1];" : "=r"(v) : "l"(f) : "memory");
    } while (v != 2);
}

__global__ void clear_flags()
{
    g_flags[blockIdx.x * 256 + threadIdx.x] = 0;
}

// ============================================================================
// Main kernel: 64 converter CTAs (bid 0..63) + 2048 GEMM CTAs (bid 64..2111)
// ============================================================================
static constexpr int TILE_BYTES  = 16384;                 // 128 x 128B
static constexpr int STAGE_BYTES = 2 * TILE_BYTES;        // A + B
static constexpr int STAGES      = 3;
static constexpr int KITERS      = 64;                    // 4096 / 64
static constexpr int NCONV       = 64;                    // converter CTAs
static constexpr int NWORK       = 96 * 64;               // (32 A + 64 B tiles) x 64 kc
static constexpr int SMEM_ALLOC  = STAGES * STAGE_BYTES + 1024;

__global__ __launch_bounds__(256, 2)
void lstm_gemm(const float* __restrict__ x,  const float* __restrict__ hin,
               const float* __restrict__ wi, const float* __restrict__ wh,
               const float* __restrict__ Bv, const float* __restrict__ Cin,
               float* __restrict__ Oh, float* __restrict__ Oc, float* __restrict__ Og)
{
    const int tid  = threadIdx.x;

    // ======================= CONVERTER PATH ================================
    if (blockIdx.x < NCONV) {
        const int m  = tid >> 1;            // row within chunk-tile: 0..127
        const int c0 = (tid & 1) * 4;       // first 8-half chunk: 0 or 4

        for (int wk = blockIdx.x; wk < NWORK; wk += NCONV) {
            const int kc = wk / 96;         // kc-major: all tiles of k before k+1
            const int t  = wk - kc * 96;    // 0..31 = A(mt), 32..95 = B(nt)
            const int kcol = (kc & 31) * 64 + c0 * 8;

            const float* src;
            __half* dstbuf;
            uint32_t tile;
            int flag_idx;
            if (t < 32) {
                src = ((kc < 32) ? x : hin) + (size_t)(t * 128 + m) * 2048 + kcol;
                dstbuf = g_Ah; tile = (uint32_t)t;
                flag_idx = t * 64 + kc;
            } else {
                const int nt = t - 32;
                const int srow = ((m >> 5) << 11) + nt * 32 + (m & 31);
                src = ((kc < 32) ? wi : wh) + (size_t)srow * 2048 + kcol;
                dstbuf = g_Bh; tile = (uint32_t)nt;
                flag_idx = 2048 + nt * 64 + kc;
            }

            float4 v[8];
            #pragma unroll
            for (int j = 0; j < 4; j++) {
                v[2*j]   = *reinterpret_cast<const float4*>(src + j * 8);
                v[2*j+1] = *reinterpret_cast<const float4*>(src + j * 8 + 4);
            }
            const uint32_t tb = (uint32_t)m * 8u + (uint32_t)kc * 1024u + tile * 65536u;
            #pragma unroll
            for (int j = 0; j < 4; j++)
                chunk_store(dstbuf, tb + (uint32_t)(c0 + j), v[2*j], v[2*j+1]);

            __threadfence();                // this thread's stores -> gpu scope
            __syncthreads();                // all 256 threads fenced
            if (tid == 0)
                asm volatile("st.release.gpu.global.u32 [%0], %1;"
                             :: "l"(&g_flags[flag_idx]), "r"(2) : "memory");
        }
        return;
    }

    // ========================= GEMM PATH ===================================
    extern __shared__ unsigned char smraw[];
    __shared__ __align__(8) unsigned long long mbar_s[2 * STAGES];  // full[3], empty[3]
    __shared__ float s_bias[128];

    const int lane = tid & 31;
    const int w    = tid >> 5;
    const int wm   = w & 1;        // 0..1  (M)
    const int wn   = w >> 1;       // 0..3  (N)
    const int gid   = blockIdx.x - NCONV;
    const int mtile = gid & 31;    // 0..31
    const int ntile = gid >> 5;    // 0..63 (h-col block of 32)

    const uint32_t smb = (smem_u32(smraw) + 1023u) & ~1023u;
    unsigned char* smal = smraw + (smb - smem_u32(smraw));
    const uint32_t mbb = smem_u32(&mbar_s[0]);     // full[s]  at mbb + s*8
    const uint32_t ebb = mbb + STAGES * 8;         // empty[s] at ebb + s*8

    if (tid == 0) {
        #pragma unroll
        for (int s = 0; s < STAGES; s++) {
            mbar_init(mbb + s * 8, 1);
            mbar_init(ebb + s * 8, 8);             // one arrive per warp
        }
    }
    if (tid < 128)
        s_bias[tid] = Bv[(size_t)((tid >> 5) << 11) + (size_t)ntile * 32 + (tid & 31)];
    __syncthreads();

    const uint64_t gA = (uint64_t)(const void*)g_Ah + (uint64_t)(mtile * 64) * TILE_BYTES;
    const uint64_t gB = (uint64_t)(const void*)g_Bh + (uint64_t)(ntile * 64) * TILE_BYTES;
    const int* fA = &g_flags[mtile * 64];
    const int* fB = &g_flags[2048 + ntile * 64];

    auto produce = [&](int it, int s) {
        poll_flag(fA + it);
        poll_flag(fB + it);
        const uint32_t mb = mbb + s * 8;
        mbar_expect(mb, (uint32_t)STAGE_BYTES);
        bulk_g2s(smb + s * STAGE_BYTES,
                 (const void*)(gA + (uint64_t)it * TILE_BYTES), TILE_BYTES, mb);
        bulk_g2s(smb + s * STAGE_BYTES + TILE_BYTES,
                 (const void*)(gB + (uint64_t)it * TILE_BYTES), TILE_BYTES, mb);
    };
    if (tid == 0) { produce(0, 0); produce(1, 1); produce(2, 2); }

    // fragment address components (byte offsets inside a 16KB tile)
    uint32_t arow[4], brow4[2], cxA[4], cxB[4];
    #pragma unroll
    for (int mi = 0; mi < 4; mi++)
        arow[mi] = (uint32_t)((wm * 64 + mi * 16 + ((lane >> 3) & 1) * 8 + (lane & 7)) << 7);
    #pragma unroll
    for (int p = 0; p < 2; p++)   // ldmatrix.x4 covering n-frag pair (2p, 2p+1)
        brow4[p] = (uint32_t)(TILE_BYTES +
                   ((wn * 32 + p * 16 + ((lane >> 4) & 1) * 8 + (lane & 7)) << 7));
    #pragma unroll
    for (int ks = 0; ks < 4; ks++) {
        cxA[ks] = (uint32_t)((((2 * ks + (lane >> 4)) ^ (lane & 7)) << 4));
        cxB[ks] = (uint32_t)((((2 * ks + ((lane >> 3) & 1)) ^ (lane & 7)) << 4));
    }

    float acc[4][4][4];
    #pragma unroll
    for (int mi = 0; mi < 4; mi++)
        #pragma unroll
        for (int ni = 0; ni < 4; ni++)
            #pragma unroll
            for (int r = 0; r < 4; r++) acc[mi][ni][r] = 0.0f;

    // one k-chunk consume: stage offsets are compile-time per call site
    auto consume = [&](uint32_t base) {
        #pragma unroll
        for (int ks = 0; ks < 4; ks++) {
            uint32_t b0[4], b1[4];
            #pragma unroll
            for (int p = 0; p < 2; p++)
                asm volatile("ldmatrix.sync.aligned.m8n8.x4.shared.b16 {%0,%1,%2,%3}, [%4];"
                             : "=r"(b0[2*p]), "=r"(b1[2*p]), "=r"(b0[2*p+1]), "=r"(b1[2*p+1])
                             : "r"(base + brow4[p] + cxB[ks]));
            #pragma unroll
            for (int mi = 0; mi < 4; mi++) {
                uint32_t a0, a1, a2, a3;
                asm volatile("ldmatrix.sync.aligned.m8n8.x4.shared.b16 {%0,%1,%2,%3}, [%4];"
                             : "=r"(a0), "=r"(a1), "=r"(a2), "=r"(a3)
                             : "r"(base + arow[mi] + cxA[ks]));
                #pragma unroll
                for (int ni = 0; ni < 4; ni++)
                    asm volatile(
                        "mma.sync.aligned.m16n8k16.row.col.f32.f16.f16.f32 "
                        "{%0,%1,%2,%3}, {%4,%5,%6,%7}, {%8,%9}, {%0,%1,%2,%3};"
                        : "+f"(acc[mi][ni][0]), "+f"(acc[mi][ni][1]),
                          "+f"(acc[mi][ni][2]), "+f"(acc[mi][ni][3])
                        : "r"(a0), "r"(a1), "r"(a2), "r"(a3),
                          "r"(b0[ni]), "r"(b1[ni]));
            }
        }
    };

    // ---- mainloop: 20 uniform trips of 3 (it 0..59), then 4-iter tail ----
    for (int trip = 0; trip < 20; trip++) {
        const uint32_t par = (uint32_t)trip & 1u;
        const int it0 = trip * 3;
        #pragma unroll
        for (int j = 0; j < STAGES; j++) {          // stage j == it % 3
            mbar_wait(mbb + j * 8, par);
            consume(smb + j * STAGE_BYTES);
            if (lane == 0) mbar_arrive(ebb + j * 8);
            if (w == j && lane == 0) {
                mbar_wait(ebb + j * 8, par);
                produce(it0 + j + STAGES, j);       // it+3 <= 62 always
            }
        }
    }
    // tail: it = 60 (st0,p0), 61 (st1,p0), 62 (st2,p0), 63 (st0,p1)
    {
        mbar_wait(mbb + 0, 0);
        consume(smb);
        if (lane == 0) mbar_arrive(ebb + 0);
        if (w == 0 && lane == 0) { mbar_wait(ebb + 0, 0); produce(63, 0); }

        mbar_wait(mbb + 8, 0);
        consume(smb + STAGE_BYTES);
        if (lane == 0) mbar_arrive(ebb + 8);

        mbar_wait(mbb + 16, 0);
        consume(smb + 2 * STAGE_BYTES);
        if (lane == 0) mbar_arrive(ebb + 16);

        mbar_wait(mbb + 0, 1);
        consume(smb);
    }

    // ------------- fused epilogue: acc -> SMEM -> gates -> outputs ---------
    __syncthreads();                               // pipeline fully drained
    float* sC = reinterpret_cast<float*>(smal);    // [128][132] fp32

    const size_t mbase = (size_t)mtile * 128;
    const size_t hb    = (size_t)ntile * 32;

    // prefetch Cin as float4 (overlaps with acc->SMEM transpose + barrier)
    float4 cin4[4];
    #pragma unroll
    for (int kk = 0; kk < 4; kk++) {
        const int idx = kk * 256 + tid;
        const int m = idx >> 3, c4 = (idx & 7) * 4;
        cin4[kk] = *reinterpret_cast<const float4*>(&Cin[(mbase + m) * 2048 + hb + c4]);
    }

    #pragma unroll
    for (int mi = 0; mi < 4; mi++) {
        const int r0 = wm * 64 + mi * 16 + (lane >> 2);
        #pragma unroll
        for (int ni = 0; ni < 4; ni++) {
            const int c0 = wn * 32 + ni * 8 + (lane & 3) * 2;
            *reinterpret_cast<float2*>(&sC[r0 * 132 + c0]) =
                make_float2(acc[mi][ni][0], acc[mi][ni][1]);
            *reinterpret_cast<float2*>(&sC[(r0 + 8) * 132 + c0]) =
                make_float2(acc[mi][ni][2], acc[mi][ni][3]);
        }
    }
    __syncthreads();

    #pragma unroll
    for (int kk = 0; kk < 4; kk++) {
        const int idx = kk * 256 + tid;
        const int m = idx >> 3, c4 = (idx & 7) * 4;
        const float* row = &sC[m * 132 + c4];

        const float4 gf = *reinterpret_cast<const float4*>(row);
        const float4 gi = *reinterpret_cast<const float4*>(row + 32);
        const float4 gs = *reinterpret_cast<const float4*>(row + 64);
        const float4 gg = *reinterpret_cast<const float4*>(row + 96);
        const float4 bf = *reinterpret_cast<const float4*>(&s_bias[c4]);
        const float4 bi = *reinterpret_cast<const float4*>(&s_bias[32 + c4]);
        const float4 bs = *reinterpret_cast<const float4*>(&s_bias[64 + c4]);
        const float4 bo = *reinterpret_cast<const float4*>(&s_bias[96 + c4]);
        const float4 cc = cin4[kk];

        float4 hn, cn, oo;
        {
            const float f = sigf(gf.x + bf.x), i = sigf(gi.x + bi.x);
            const float s = tanhp(gs.x + bs.x), o = sigf(gg.x + bo.x);
            cn.x = f * cc.x + i * s; hn.x = o * tanhp(cn.x); oo.x = o;
        }
        {
            const float f = sigf(gf.y + bf.y), i = sigf(gi.y + bi.y);
            const float s = tanhp(gs.y + bs.y), o = sigf(gg.y + bo.y);
            cn.y = f * cc.y + i * s; hn.y = o * tanhp(cn.y); oo.y = o;
        }
        {
            const float f = sigf(gf.z + bf.z), i = sigf(gi.z + bi.z);
            const float s = tanhp(gs.z + bs.z), o = sigf(gg.z + bo.z);
            cn.z = f * cc.z + i * s; hn.z = o * tanhp(cn.z); oo.z = o;
        }
        {
            const float f = sigf(gf.w + bf.w), i = sigf(gi.w + bi.w);
            const float s = tanhp(gs.w + bs.w), o = sigf(gg.w + bo.w);
            cn.w = f * cc.w + i * s; hn.w = o * tanhp(cn.w); oo.w = o;
        }

        const size_t off = (mbase + m) * 2048 + hb + c4;
        *reinterpret_cast<float4*>(&Oh[off]) = hn;
        *reinterpret_cast<float4*>(&Oc[off]) = cn;
        *reinterpret_cast<float4*>(&Og[off]) = oo;
    }
}

// ============================================================================
// launch
// ============================================================================
extern "C" void kernel_launch(void* const* d_in, const int* in_sizes, int n_in,
                              void* d_out, int out_size)
{
    const float* x    = (const float*)d_in[0];
    const float* h    = (const float*)d_in[1];
    const float* c    = (const float*)d_in[2];
    /* d_in[3] = o, unused by the reference computation */
    const float* w_ih = (const float*)d_in[4];
    const float* w_hh = (const float*)d_in[5];
    const float* b    = (const float*)d_in[6];
    float* out = (float*)d_out;

    cudaFuncSetAttribute(lstm_gemm,
                         cudaFuncAttributeMaxDynamicSharedMemorySize, SMEM_ALLOC);

    clear_flags<<<32, 256>>>();

    float* out_h  = out;
    float* out_c  = out + (size_t)4096 * 2048;
    float* out_go = out + (size_t)2 * 4096 * 2048;
    lstm_gemm<<<2048 + NCONV, 256, SMEM_ALLOC>>>(x, h, w_ih, w_hh, b, c,
                                                 out_h, out_c, out_go);
}

// round 14
// speedup vs baseline: 1.3395x; 1.3395x over previous
#include <cuda_runtime.h>
#include <cuda_fp16.h>
#include <cstdint>

// ============================================================================
// LSTMCell for GB300 — sm_103 (non-'a') path: fp16 mma.sync + cp.async.bulk.
//
//   Pass 1: fp32 -> fp16 (RN), pre-tiled + SW128-swizzled, MLP=8 loads.
//   Pass 2: GEMM 256x128x(BK=64) — warp tile 64x64 (4Mx2N warps) to cut
//           SMEM crossbar traffic 33%/output (smem was saturated at the
//           128x128/64x32 shape).  1 CTA/SM, 3-stage bulk-copy mbarrier
//           ring, trip-unrolled, round-robin producer, float4 LSTM epilogue.
// ============================================================================

#define DINLINE __device__ __forceinline__

__device__ __align__(1024) __half g_Ah[4096UL * 4096];   // 32 MB
__device__ __align__(1024) __half g_Bh[8192UL * 4096];   // 64 MB

// ------------------------------- helpers -----------------------------------
DINLINE uint32_t smem_u32(const void* p) {
    uint32_t a;
    asm("{ .reg .u64 t; cvta.to.shared.u64 t, %1; cvt.u32.u64 %0, t; }"
        : "=r"(a) : "l"(p));
    return a;
}

DINLINE void mbar_init(uint32_t a, uint32_t cnt) {
    asm volatile("mbarrier.init.shared.b64 [%0], %1;" :: "r"(a), "r"(cnt) : "memory");
}
DINLINE void mbar_expect(uint32_t a, uint32_t tx) {
    asm volatile("mbarrier.arrive.expect_tx.shared.b64 _, [%0], %1;"
                 :: "r"(a), "r"(tx) : "memory");
}
DINLINE void mbar_arrive(uint32_t a) {
    asm volatile("mbarrier.arrive.shared.b64 _, [%0];" :: "r"(a) : "memory");
}
DINLINE void mbar_wait(uint32_t mbar, uint32_t parity) {
    uint32_t done;
    asm volatile(
        "{\n .reg .pred p;\n"
        " mbarrier.try_wait.parity.acquire.cta.shared::cta.b64 p, [%1], %2;\n"
        " selp.b32 %0, 1, 0, p;\n}"
        : "=r"(done) : "r"(mbar), "r"(parity) : "memory");
    if (!done) {
        asm volatile(
            "{\n .reg .pred P1;\n"
            "WL%=:\n"
            " mbarrier.try_wait.parity.acquire.cta.shared::cta.b64 P1, [%0], %1, 0x989680;\n"
            " @P1 bra.uni WD%=;\n"
            " bra.uni WL%=;\n"
            "WD%=:\n}"
            :: "r"(mbar), "r"(parity) : "memory");
    }
}

DINLINE void bulk_g2s(uint32_t dst, const void* src, uint32_t bytes, uint32_t mbar) {
    asm volatile(
        "cp.async.bulk.shared::cluster.global.mbarrier::complete_tx::bytes [%0], [%1], %2, [%3];"
        :: "r"(dst), "l"(src), "r"(bytes), "r"(mbar) : "memory");
}

// fast-math gates (ex2/rcp approx; errors ~1e-7, negligible vs fp16 inputs)
DINLINE float ex2a(float x) { float y; asm("ex2.approx.f32 %0, %1;" : "=f"(y) : "f"(x)); return y; }
DINLINE float rcpa(float x) { float y; asm("rcp.approx.f32 %0, %1;" : "=f"(y) : "f"(x)); return y; }
DINLINE float sigf(float x)  { return rcpa(1.0f + ex2a(-1.442695041f * x)); }
DINLINE float tanhp(float x) { return 2.0f * sigf(2.0f * x) - 1.0f; }

// ============================================================================
// Pass 1: convert + tile + swizzle.  Chunk = 16B of fp16 (8 halves).
//   chunk id bits: [c:3][m:7][kc:6][tile:rest]
//   4 chunks per thread, all 8 LDG.128 issued before converts (MLP=8).
// ============================================================================
DINLINE const float* chunk_src(const float* a, const float* b,
                               uint32_t t, int which)
{
    const uint32_t c = t & 7u;
    const uint32_t m = (t >> 3) & 127u;
    const uint32_t k = ((t >> 10) & 63u) * 64u + c * 8u;
    const uint32_t tile = t >> 16;
    uint32_t src_row;
    if (which) src_row = ((m >> 5) << 11) + tile * 32u + (m & 31u);
    else       src_row = tile * 128u + m;
    const size_t srow = (size_t)src_row * 2048;
    return (k < 2048u) ? (a + srow + k) : (b + srow + (k - 2048u));
}

DINLINE void chunk_store(__half* dstbuf, uint32_t t,
                         const float4& v0, const float4& v1)
{
    __half2 h0 = __floats2half2_rn(v0.x, v0.y);
    __half2 h1 = __floats2half2_rn(v0.z, v0.w);
    __half2 h2 = __floats2half2_rn(v1.x, v1.y);
    __half2 h3 = __floats2half2_rn(v1.z, v1.w);
    uint4 out;
    out.x = *reinterpret_cast<uint32_t*>(&h0);
    out.y = *reinterpret_cast<uint32_t*>(&h1);
    out.z = *reinterpret_cast<uint32_t*>(&h2);
    out.w = *reinterpret_cast<uint32_t*>(&h3);
    const uint32_t c = t & 7u, m = (t >> 3) & 127u;
    *reinterpret_cast<uint4*>((unsigned char*)dstbuf +
        ((size_t)(t >> 3) << 7) + ((c ^ (m & 7u)) << 4)) = out;
}

__global__ __launch_bounds__(256)
void cvt_pack(const float* __restrict__ x,  const float* __restrict__ h,
              const float* __restrict__ wi, const float* __restrict__ wh)
{
    const uint32_t g = blockIdx.x * 256u + threadIdx.x;
    float4 v[8];
    uint32_t t[4];

    if (g < (1u << 19)) {
        #pragma unroll
        for (int j = 0; j < 4; j++) t[j] = g + (uint32_t)j * (1u << 19);
        #pragma unroll
        for (int j = 0; j < 4; j++) {
            const float* s = chunk_src(x, h, t[j], 0);
            v[2*j]   = *reinterpret_cast<const float4*>(s);
            v[2*j+1] = *reinterpret_cast<const float4*>(s + 4);
        }
        #pragma unroll
        for (int j = 0; j < 4; j++) chunk_store(g_Ah, t[j], v[2*j], v[2*j+1]);
    } else {
        const uint32_t q = g - (1u << 19);
        #pragma unroll
        for (int j = 0; j < 4; j++) t[j] = q + (uint32_t)j * (1u << 20);
        #pragma unroll
        for (int j = 0; j < 4; j++) {
            const float* s = chunk_src(wi, wh, t[j], 1);
            v[2*j]   = *reinterpret_cast<const float4*>(s);
            v[2*j+1] = *reinterpret_cast<const float4*>(s + 4);
        }
        #pragma unroll
        for (int j = 0; j < 4; j++) chunk_store(g_Bh, t[j], v[2*j], v[2*j+1]);
    }
}

// ============================================================================
// Pass 2: fused GEMM + LSTM cell.
//   CTA tile 256(M) x 128(packed N = 4 gates x 32 h-cols), BK=64.
//   8 warps 4(M) x 2(N); warp tile 64x64; mma m16n8k16 fp16->fp32.
//   Stage = [A0 16KB | A1 16KB | B 16KB] = 48KB; 3 stages; 1 CTA/SM.
// ============================================================================
static constexpr int CHUNK_BYTES = 16384;                 // 128 rows x 128B
static constexpr int STAGE_BYTES = 3 * CHUNK_BYTES;       // A0 + A1 + B
static constexpr int STAGES      = 3;
static constexpr int KITERS      = 64;                    // 4096 / 64
static constexpr int SMEM_ALLOC  = STAGES * STAGE_BYTES + 1024;   // 148480

__global__ __launch_bounds__(256, 1)
void lstm_gemm(const float* __restrict__ Bv, const float* __restrict__ Cin,
               float* __restrict__ Oh, float* __restrict__ Oc, float* __restrict__ Og)
{
    extern __shared__ unsigned char smraw[];
    __shared__ __align__(8) unsigned long long mbar_s[2 * STAGES];  // full[3], empty[3]
    __shared__ float s_bias[128];

    const int tid  = threadIdx.x;
    const int lane = tid & 31;
    const int w    = tid >> 5;
    const int wm   = w & 3;        // 0..3  (M)
    const int wn   = w >> 2;       // 0..1  (N)
    const int mtile = blockIdx.x & 15;   // 0..15  (256-row tiles)
    const int ntile = blockIdx.x >> 4;   // 0..63  (h-col block of 32)

    const uint32_t smb = (smem_u32(smraw) + 1023u) & ~1023u;
    unsigned char* smal = smraw + (smb - smem_u32(smraw));
    const uint32_t mbb = smem_u32(&mbar_s[0]);     // full[s]  at mbb + s*8
    const uint32_t ebb = mbb + STAGES * 8;         // empty[s] at ebb + s*8

    if (tid == 0) {
        #pragma unroll
        for (int s = 0; s < STAGES; s++) {
            mbar_init(mbb + s * 8, 1);
            mbar_init(ebb + s * 8, 8);             // one arrive per warp
        }
    }
    if (tid < 128)
        s_bias[tid] = Bv[(size_t)((tid >> 5) << 11) + (size_t)ntile * 32 + (tid & 31)];
    __syncthreads();

    // A chunks (old 128-row layout): tile pair (2*mtile, 2*mtile+1)
    const uint64_t gA0 = (uint64_t)(const void*)g_Ah
                       + (uint64_t)(mtile * 128) * CHUNK_BYTES;        // mt128=2*mtile
    const uint64_t gA1 = gA0 + (uint64_t)64 * CHUNK_BYTES;             // mt128=2*mtile+1
    const uint64_t gB  = (uint64_t)(const void*)g_Bh
                       + (uint64_t)(ntile * 64) * CHUNK_BYTES;

    auto produce = [&](int it, int s) {
        const uint32_t mb = mbb + s * 8;
        mbar_expect(mb, (uint32_t)STAGE_BYTES);
        const uint32_t dst = smb + s * STAGE_BYTES;
        bulk_g2s(dst,                   (const void*)(gA0 + (uint64_t)it * CHUNK_BYTES),
                 CHUNK_BYTES, mb);
        bulk_g2s(dst + CHUNK_BYTES,     (const void*)(gA1 + (uint64_t)it * CHUNK_BYTES),
                 CHUNK_BYTES, mb);
        bulk_g2s(dst + 2 * CHUNK_BYTES, (const void*)(gB  + (uint64_t)it * CHUNK_BYTES),
                 CHUNK_BYTES, mb);
    };
    if (tid == 0) { produce(0, 0); produce(1, 1); produce(2, 2); }

    // fragment address components (byte offsets inside a 48KB stage)
    // Warp wm covers rows [wm*64, wm*64+64): wm 0,1 -> A0 region; wm 2,3 -> A1.
    uint32_t arow[4], brow4[4], cxA[4], cxB[4];
    {
        const uint32_t aoff = (wm >= 2) ? (uint32_t)CHUNK_BYTES : 0u;
        #pragma unroll
        for (int mi = 0; mi < 4; mi++)
            arow[mi] = aoff + (uint32_t)((((wm & 1) * 64) + mi * 16 +
                       ((lane >> 3) & 1) * 8 + (lane & 7)) << 7);
    }
    #pragma unroll
    for (int p = 0; p < 4; p++)   // ldmatrix.x4 covering n-frag pair (2p, 2p+1)
        brow4[p] = (uint32_t)(2 * CHUNK_BYTES +
                   ((wn * 64 + p * 16 + ((lane >> 4) & 1) * 8 + (lane & 7)) << 7));
    #pragma unroll
    for (int ks = 0; ks < 4; ks++) {
        cxA[ks] = (uint32_t)((((2 * ks + (lane >> 4)) ^ (lane & 7)) << 4));
        cxB[ks] = (uint32_t)((((2 * ks + ((lane >> 3) & 1)) ^ (lane & 7)) << 4));
    }

    float acc[4][8][4];
    #pragma unroll
    for (int mi = 0; mi < 4; mi++)
        #pragma unroll
        for (int ni = 0; ni < 8; ni++)
            #pragma unroll
            for (int r = 0; r < 4; r++) acc[mi][ni][r] = 0.0f;

    // one k-chunk consume: stage offsets are compile-time per call site
    auto consume = [&](uint32_t base) {
        #pragma unroll
        for (int ks = 0; ks < 4; ks++) {
            uint32_t b0[8], b1[8];
            #pragma unroll
            for (int p = 0; p < 4; p++)
                asm volatile("ldmatrix.sync.aligned.m8n8.x4.shared.b16 {%0,%1,%2,%3}, [%4];"
                             : "=r"(b0[2*p]), "=r"(b1[2*p]), "=r"(b0[2*p+1]), "=r"(b1[2*p+1])
                             : "r"(base + brow4[p] + cxB[ks]));
            #pragma unroll
            for (int mi = 0; mi < 4; mi++) {
                uint32_t a0, a1, a2, a3;
                asm volatile("ldmatrix.sync.aligned.m8n8.x4.shared.b16 {%0,%1,%2,%3}, [%4];"
                             : "=r"(a0), "=r"(a1), "=r"(a2), "=r"(a3)
                             : "r"(base + arow[mi] + cxA[ks]));
                #pragma unroll
                for (int ni = 0; ni < 8; ni++)
                    asm volatile(
                        "mma.sync.aligned.m16n8k16.row.col.f32.f16.f16.f32 "
                        "{%0,%1,%2,%3}, {%4,%5,%6,%7}, {%8,%9}, {%0,%1,%2,%3};"
                        : "+f"(acc[mi][ni][0]), "+f"(acc[mi][ni][1]),
                          "+f"(acc[mi][ni][2]), "+f"(acc[mi][ni][3])
                        : "r"(a0), "r"(a1), "r"(a2), "r"(a3),
                          "r"(b0[ni]), "r"(b1[ni]));
            }
        }
    };

    // ---- mainloop: 20 uniform trips of 3 (it 0..59), then 4-iter tail ----
    for (int trip = 0; trip < 20; trip++) {
        const uint32_t par = (uint32_t)trip & 1u;
        const int it0 = trip * 3;
        #pragma unroll
        for (int j = 0; j < STAGES; j++) {          // stage j == it % 3
            mbar_wait(mbb + j * 8, par);
            consume(smb + j * STAGE_BYTES);
            if (lane == 0) mbar_arrive(ebb + j * 8);
            if (w == j && lane == 0) {
                mbar_wait(ebb + j * 8, par);
                produce(it0 + j + STAGES, j);       // it+3 <= 62 always
            }
        }
    }
    // tail: it = 60 (st0,p0), 61 (st1,p0), 62 (st2,p0), 63 (st0,p1)
    {
        mbar_wait(mbb + 0, 0);
        consume(smb);
        if (lane == 0) mbar_arrive(ebb + 0);
        if (w == 0 && lane == 0) { mbar_wait(ebb + 0, 0); produce(63, 0); }

        mbar_wait(mbb + 8, 0);
        consume(smb + STAGE_BYTES);
        if (lane == 0) mbar_arrive(ebb + 8);

        mbar_wait(mbb + 16, 0);
        consume(smb + 2 * STAGE_BYTES);
        if (lane == 0) mbar_arrive(ebb + 16);

        mbar_wait(mbb + 0, 1);
        consume(smb);
    }

    // ------------- fused epilogue: acc -> SMEM -> gates -> outputs ---------
    // sC = [256][132] fp32 = 135168 B, fits in the 144KB stage region.
    __syncthreads();                               // pipeline fully drained
    float* sC = reinterpret_cast<float*>(smal);

    const size_t mbase = (size_t)mtile * 256;
    const size_t hb    = (size_t)ntile * 32;

    #pragma unroll
    for (int mi = 0; mi < 4; mi++) {
        const int r0 = wm * 64 + mi * 16 + (lane >> 2);
        #pragma unroll
        for (int ni = 0; ni < 8; ni++) {
            const int c0 = wn * 64 + ni * 8 + (lane & 3) * 2;
            *reinterpret_cast<float2*>(&sC[r0 * 132 + c0]) =
                make_float2(acc[mi][ni][0], acc[mi][ni][1]);
            *reinterpret_cast<float2*>(&sC[(r0 + 8) * 132 + c0]) =
                make_float2(acc[mi][ni][2], acc[mi][ni][3]);
        }
    }

    // prefetch Cin as float4 (latency hidden under the barrier below)
    float4 cin4[8];
    #pragma unroll
    for (int kk = 0; kk < 8; kk++) {
        const int idx = kk * 256 + tid;
        const int m = idx >> 3, c4 = (idx & 7) * 4;
        cin4[kk] = *reinterpret_cast<const float4*>(&Cin[(mbase + m) * 2048 + hb + c4]);
    }
    __syncthreads();

    #pragma unroll
    for (int kk = 0; kk < 8; kk++) {
        const int idx = kk * 256 + tid;
        const int m = idx >> 3, c4 = (idx & 7) * 4;
        const float* row = &sC[m * 132 + c4];

        const float4 gf = *reinterpret_cast<const float4*>(row);
        const float4 gi = *reinterpret_cast<const float4*>(row + 32);
        const float4 gs = *reinterpret_cast<const float4*>(row + 64);
        const float4 gg = *reinterpret_cast<const float4*>(row + 96);
        const float4 bf = *reinterpret_cast<const float4*>(&s_bias[c4]);
        const float4 bi = *reinterpret_cast<const float4*>(&s_bias[32 + c4]);
        const float4 bs = *reinterpret_cast<const float4*>(&s_bias[64 + c4]);
        const float4 bo = *reinterpret_cast<const float4*>(&s_bias[96 + c4]);
        const float4 cc = cin4[kk];

        float4 hn, cn, oo;
        {
            const float f = sigf(gf.x + bf.x), i = sigf(gi.x + bi.x);
            const float s = tanhp(gs.x + bs.x), o = sigf(gg.x + bo.x);
            cn.x = f * cc.x + i * s; hn.x = o * tanhp(cn.x); oo.x = o;
        }
        {
            const float f = sigf(gf.y + bf.y), i = sigf(gi.y + bi.y);
            const float s = tanhp(gs.y + bs.y), o = sigf(gg.y + bo.y);
            cn.y = f * cc.y + i * s; hn.y = o * tanhp(cn.y); oo.y = o;
        }
        {
            const float f = sigf(gf.z + bf.z), i = sigf(gi.z + bi.z);
            const float s = tanhp(gs.z + bs.z), o = sigf(gg.z + bo.z);
            cn.z = f * cc.z + i * s; hn.z = o * tanhp(cn.z); oo.z = o;
        }
        {
            const float f = sigf(gf.w + bf.w), i = sigf(gi.w + bi.w);
            const float s = tanhp(gs.w + bs.w), o = sigf(gg.w + bo.w);
            cn.w = f * cc.w + i * s; hn.w = o * tanhp(cn.w); oo.w = o;
        }

        const size_t off = (mbase + m) * 2048 + hb + c4;
        *reinterpret_cast<float4*>(&Oh[off]) = hn;
        *reinterpret_cast<float4*>(&Oc[off]) = cn;
        *reinterpret_cast<float4*>(&Og[off]) = oo;
    }
}

// ============================================================================
// launch
// ============================================================================
extern "C" void kernel_launch(void* const* d_in, const int* in_sizes, int n_in,
                              void* d_out, int out_size)
{
    const float* x    = (const float*)d_in[0];
    const float* h    = (const float*)d_in[1];
    const float* c    = (const float*)d_in[2];
    /* d_in[3] = o, unused by the reference computation */
    const float* w_ih = (const float*)d_in[4];
    const float* w_hh = (const float*)d_in[5];
    const float* b    = (const float*)d_in[6];
    float* out = (float*)d_out;

    cudaFuncSetAttribute(lstm_gemm,
                         cudaFuncAttributeMaxDynamicSharedMemorySize, SMEM_ALLOC);

    cvt_pack<<<6144, 256>>>(x, h, w_ih, w_hh);

    float* out_h  = out;
    float* out_c  = out + (size_t)4096 * 2048;
    float* out_go = out + (size_t)2 * 4096 * 2048;
    lstm_gemm<<<1024, 256, SMEM_ALLOC>>>(b, c, out_h, out_c, out_go);
}

// round 15
// speedup vs baseline: 1.3757x; 1.0271x over previous
#include <cuda_runtime.h>
#include <cuda_fp16.h>
#include <cstdint>

// ============================================================================
// LSTMCell for GB300 — sm_103 (non-'a') path: fp16 mma.sync + cp.async.bulk.
//
//   Pass 1: fp32 -> fp16 (RN), pre-tiled + SW128-swizzled, MLP=8 loads,
//           streaming (__ldcs) source reads to preserve fp16 output in L2.
//   Pass 2: GEMM 128x128x(BK=64), 3-stage bulk-copy mbarrier ring with
//           trip-level unroll (compile-time stage offsets/parities) and
//           round-robin producer (stage j refilled by warp j, lane 0),
//           fused fast-math LSTM epilogue, fully float4-vectorized.
//   (R12 config — empirically best of 5 structural variants tested.)
// ============================================================================

#define DINLINE __device__ __forceinline__

__device__ __align__(1024) __half g_Ah[4096UL * 4096];   // 32 MB
__device__ __align__(1024) __half g_Bh[8192UL * 4096];   // 64 MB

// ------------------------------- helpers -----------------------------------
DINLINE uint32_t smem_u32(const void* p) {
    uint32_t a;
    asm("{ .reg .u64 t; cvta.to.shared.u64 t, %1; cvt.u32.u64 %0, t; }"
        : "=r"(a) : "l"(p));
    return a;
}

DINLINE void mbar_init(uint32_t a, uint32_t cnt) {
    asm volatile("mbarrier.init.shared.b64 [%0], %1;" :: "r"(a), "r"(cnt) : "memory");
}
DINLINE void mbar_expect(uint32_t a, uint32_t tx) {
    asm volatile("mbarrier.arrive.expect_tx.shared.b64 _, [%0], %1;"
                 :: "r"(a), "r"(tx) : "memory");
}
DINLINE void mbar_arrive(uint32_t a) {
    asm volatile("mbarrier.arrive.shared.b64 _, [%0];" :: "r"(a) : "memory");
}
DINLINE void mbar_wait(uint32_t mbar, uint32_t parity) {
    uint32_t done;
    asm volatile(
        "{\n .reg .pred p;\n"
        " mbarrier.try_wait.parity.acquire.cta.shared::cta.b64 p, [%1], %2;\n"
        " selp.b32 %0, 1, 0, p;\n}"
        : "=r"(done) : "r"(mbar), "r"(parity) : "memory");
    if (!done) {
        asm volatile(
            "{\n .reg .pred P1;\n"
            "WL%=:\n"
            " mbarrier.try_wait.parity.acquire.cta.shared::cta.b64 P1, [%0], %1, 0x989680;\n"
            " @P1 bra.uni WD%=;\n"
            " bra.uni WL%=;\n"
            "WD%=:\n}"
            :: "r"(mbar), "r"(parity) : "memory");
    }
}

DINLINE void bulk_g2s(uint32_t dst, const void* src, uint32_t bytes, uint32_t mbar) {
    asm volatile(
        "cp.async.bulk.shared::cluster.global.mbarrier::complete_tx::bytes [%0], [%1], %2, [%3];"
        :: "r"(dst), "l"(src), "r"(bytes), "r"(mbar) : "memory");
}

// fast-math gates (ex2/rcp approx; errors ~1e-7, negligible vs fp16 inputs)
DINLINE float ex2a(float x) { float y; asm("ex2.approx.f32 %0, %1;" : "=f"(y) : "f"(x)); return y; }
DINLINE float rcpa(float x) { float y; asm("rcp.approx.f32 %0, %1;" : "=f"(y) : "f"(x)); return y; }
DINLINE float sigf(float x)  { return rcpa(1.0f + ex2a(-1.442695041f * x)); }
DINLINE float tanhp(float x) { return 2.0f * sigf(2.0f * x) - 1.0f; }

// ============================================================================
// Pass 1: convert + tile + swizzle.  Chunk = 16B of fp16 (8 halves).
//   chunk id bits: [c:3][m:7][kc:6][tile:rest]
//   4 chunks per thread, all 8 LDG.128 issued before converts (MLP=8).
//   Source reads use __ldcs (evict-first): fp32 input is single-use; keeps
//   the fp16 output resident in L2 for the GEMM that follows.
// ============================================================================
DINLINE const float* chunk_src(const float* a, const float* b,
                               uint32_t t, int which)
{
    const uint32_t c = t & 7u;
    const uint32_t m = (t >> 3) & 127u;
    const uint32_t k = ((t >> 10) & 63u) * 64u + c * 8u;
    const uint32_t tile = t >> 16;
    uint32_t src_row;
    if (which) src_row = ((m >> 5) << 11) + tile * 32u + (m & 31u);
    else       src_row = tile * 128u + m;
    const size_t srow = (size_t)src_row * 2048;
    return (k < 2048u) ? (a + srow + k) : (b + srow + (k - 2048u));
}

DINLINE void chunk_store(__half* dstbuf, uint32_t t,
                         const float4& v0, const float4& v1)
{
    __half2 h0 = __floats2half2_rn(v0.x, v0.y);
    __half2 h1 = __floats2half2_rn(v0.z, v0.w);
    __half2 h2 = __floats2half2_rn(v1.x, v1.y);
    __half2 h3 = __floats2half2_rn(v1.z, v1.w);
    uint4 out;
    out.x = *reinterpret_cast<uint32_t*>(&h0);
    out.y = *reinterpret_cast<uint32_t*>(&h1);
    out.z = *reinterpret_cast<uint32_t*>(&h2);
    out.w = *reinterpret_cast<uint32_t*>(&h3);
    const uint32_t c = t & 7u, m = (t >> 3) & 127u;
    *reinterpret_cast<uint4*>((unsigned char*)dstbuf +
        ((size_t)(t >> 3) << 7) + ((c ^ (m & 7u)) << 4)) = out;
}

__global__ __launch_bounds__(256)
void cvt_pack(const float* __restrict__ x,  const float* __restrict__ h,
              const float* __restrict__ wi, const float* __restrict__ wh)
{
    const uint32_t g = blockIdx.x * 256u + threadIdx.x;
    float4 v[8];
    uint32_t t[4];

    if (g < (1u << 19)) {
        #pragma unroll
        for (int j = 0; j < 4; j++) t[j] = g + (uint32_t)j * (1u << 19);
        #pragma unroll
        for (int j = 0; j < 4; j++) {
            const float* s = chunk_src(x, h, t[j], 0);
            v[2*j]   = __ldcs(reinterpret_cast<const float4*>(s));
            v[2*j+1] = __ldcs(reinterpret_cast<const float4*>(s + 4));
        }
        #pragma unroll
        for (int j = 0; j < 4; j++) chunk_store(g_Ah, t[j], v[2*j], v[2*j+1]);
    } else {
        const uint32_t q = g - (1u << 19);
        #pragma unroll
        for (int j = 0; j < 4; j++) t[j] = q + (uint32_t)j * (1u << 20);
        #pragma unroll
        for (int j = 0; j < 4; j++) {
            const float* s = chunk_src(wi, wh, t[j], 1);
            v[2*j]   = __ldcs(reinterpret_cast<const float4*>(s));
            v[2*j+1] = __ldcs(reinterpret_cast<const float4*>(s + 4));
        }
        #pragma unroll
        for (int j = 0; j < 4; j++) chunk_store(g_Bh, t[j], v[2*j], v[2*j+1]);
    }
}

// ============================================================================
// Pass 2: fused GEMM + LSTM cell.
//   CTA tile 128(M) x 128(packed N = 4 gates x 32 h-cols), BK=64.
//   8 warps 2(M) x 4(N); warp tile 64x32; mma m16n8k16 fp16->fp32.
//   Pipeline: full[s] (tx mbarrier) + empty[s] (count-8, per-warp arrive).
//   Mainloop unrolled by ring depth; producer round-robin (warp j, stage j).
// ============================================================================
static constexpr int TILE_BYTES  = 16384;                 // 128 x 128B
static constexpr int STAGE_BYTES = 2 * TILE_BYTES;        // A + B
static constexpr int STAGES      = 3;
static constexpr int KITERS      = 64;                    // 4096 / 64
static constexpr int SMEM_ALLOC  = STAGES * STAGE_BYTES + 1024;

__global__ __launch_bounds__(256, 2)
void lstm_gemm(const float* __restrict__ Bv, const float* __restrict__ Cin,
               float* __restrict__ Oh, float* __restrict__ Oc, float* __restrict__ Og)
{
    extern __shared__ unsigned char smraw[];
    __shared__ __align__(8) unsigned long long mbar_s[2 * STAGES];  // full[3], empty[3]
    __shared__ float s_bias[128];

    const int tid  = threadIdx.x;
    const int lane = tid & 31;
    const int w    = tid >> 5;
    const int wm   = w & 1;        // 0..1  (M)
    const int wn   = w >> 1;       // 0..3  (N)
    const int mtile = blockIdx.x & 31;   // 0..31
    const int ntile = blockIdx.x >> 5;   // 0..63 (h-col block of 32)

    const uint32_t smb = (smem_u32(smraw) + 1023u) & ~1023u;
    unsigned char* smal = smraw + (smb - smem_u32(smraw));
    const uint32_t mbb = smem_u32(&mbar_s[0]);     // full[s]  at mbb + s*8
    const uint32_t ebb = mbb + STAGES * 8;         // empty[s] at ebb + s*8

    if (tid == 0) {
        #pragma unroll
        for (int s = 0; s < STAGES; s++) {
            mbar_init(mbb + s * 8, 1);
            mbar_init(ebb + s * 8, 8);             // one arrive per warp
        }
    }
    if (tid < 128)
        s_bias[tid] = Bv[(size_t)((tid >> 5) << 11) + (size_t)ntile * 32 + (tid & 31)];
    __syncthreads();

    const uint64_t gA = (uint64_t)(const void*)g_Ah + (uint64_t)(mtile * 64) * TILE_BYTES;
    const uint64_t gB = (uint64_t)(const void*)g_Bh + (uint64_t)(ntile * 64) * TILE_BYTES;

    auto produce = [&](int it, int s) {
        const uint32_t mb = mbb + s * 8;
        mbar_expect(mb, (uint32_t)STAGE_BYTES);
        bulk_g2s(smb + s * STAGE_BYTES,
                 (const void*)(gA + (uint64_t)it * TILE_BYTES), TILE_BYTES, mb);
        bulk_g2s(smb + s * STAGE_BYTES + TILE_BYTES,
                 (const void*)(gB + (uint64_t)it * TILE_BYTES), TILE_BYTES, mb);
    };
    if (tid == 0) { produce(0, 0); produce(1, 1); produce(2, 2); }

    // fragment address components (byte offsets inside a 16KB tile)
    uint32_t arow[4], brow4[2], cxA[4], cxB[4];
    #pragma unroll
    for (int mi = 0; mi < 4; mi++)
        arow[mi] = (uint32_t)((wm * 64 + mi * 16 + ((lane >> 3) & 1) * 8 + (lane & 7)) << 7);
    #pragma unroll
    for (int p = 0; p < 2; p++)   // ldmatrix.x4 covering n-frag pair (2p, 2p+1)
        brow4[p] = (uint32_t)(TILE_BYTES +
                   ((wn * 32 + p * 16 + ((lane >> 4) & 1) * 8 + (lane & 7)) << 7));
    #pragma unroll
    for (int ks = 0; ks < 4; ks++) {
        cxA[ks] = (uint32_t)((((2 * ks + (lane >> 4)) ^ (lane & 7)) << 4));
        cxB[ks] = (uint32_t)((((2 * ks + ((lane >> 3) & 1)) ^ (lane & 7)) << 4));
    }

    float acc[4][4][4];
    #pragma unroll
    for (int mi = 0; mi < 4; mi++)
        #pragma unroll
        for (int ni = 0; ni < 4; ni++)
            #pragma unroll
            for (int r = 0; r < 4; r++) acc[mi][ni][r] = 0.0f;

    // one k-chunk consume: stage offsets are compile-time per call site
    auto consume = [&](uint32_t base) {
        #pragma unroll
        for (int ks = 0; ks < 4; ks++) {
            uint32_t b0[4], b1[4];
            #pragma unroll
            for (int p = 0; p < 2; p++)
                asm volatile("ldmatrix.sync.aligned.m8n8.x4.shared.b16 {%0,%1,%2,%3}, [%4];"
                             : "=r"(b0[2*p]), "=r"(b1[2*p]), "=r"(b0[2*p+1]), "=r"(b1[2*p+1])
                             : "r"(base + brow4[p] + cxB[ks]));
            #pragma unroll
            for (int mi = 0; mi < 4; mi++) {
                uint32_t a0, a1, a2, a3;
                asm volatile("ldmatrix.sync.aligned.m8n8.x4.shared.b16 {%0,%1,%2,%3}, [%4];"
                             : "=r"(a0), "=r"(a1), "=r"(a2), "=r"(a3)
                             : "r"(base + arow[mi] + cxA[ks]));
                #pragma unroll
                for (int ni = 0; ni < 4; ni++)
                    asm volatile(
                        "mma.sync.aligned.m16n8k16.row.col.f32.f16.f16.f32 "
                        "{%0,%1,%2,%3}, {%4,%5,%6,%7}, {%8,%9}, {%0,%1,%2,%3};"
                        : "+f"(acc[mi][ni][0]), "+f"(acc[mi][ni][1]),
                          "+f"(acc[mi][ni][2]), "+f"(acc[mi][ni][3])
                        : "r"(a0), "r"(a1), "r"(a2), "r"(a3),
                          "r"(b0[ni]), "r"(b1[ni]));
            }
        }
    };

    // ---- mainloop: 20 uniform trips of 3 (it 0..59), then 4-iter tail ----
    for (int trip = 0; trip < 20; trip++) {
        const uint32_t par = (uint32_t)trip & 1u;
        const int it0 = trip * 3;
        #pragma unroll
        for (int j = 0; j < STAGES; j++) {          // stage j == it % 3
            mbar_wait(mbb + j * 8, par);
            consume(smb + j * STAGE_BYTES);
            if (lane == 0) mbar_arrive(ebb + j * 8);
            if (w == j && lane == 0) {
                mbar_wait(ebb + j * 8, par);
                produce(it0 + j + STAGES, j);       // it+3 <= 62 always
            }
        }
    }
    // tail: it = 60 (st0,p0), 61 (st1,p0), 62 (st2,p0), 63 (st0,p1)
    {
        mbar_wait(mbb + 0, 0);
        consume(smb);
        if (lane == 0) mbar_arrive(ebb + 0);
        if (w == 0 && lane == 0) { mbar_wait(ebb + 0, 0); produce(63, 0); }

        mbar_wait(mbb + 8, 0);
        consume(smb + STAGE_BYTES);
        if (lane == 0) mbar_arrive(ebb + 8);

        mbar_wait(mbb + 16, 0);
        consume(smb + 2 * STAGE_BYTES);
        if (lane == 0) mbar_arrive(ebb + 16);

        mbar_wait(mbb + 0, 1);
        consume(smb);
    }

    // ------------- fused epilogue: acc -> SMEM -> gates -> outputs ---------
    // Fully float4-vectorized: 4 kk-iterations, LDS.128/LDG.128/STG.128.
    __syncthreads();                               // pipeline fully drained
    float* sC = reinterpret_cast<float*>(smal);    // [128][132] fp32

    const size_t mbase = (size_t)mtile * 128;
    const size_t hb    = (size_t)ntile * 32;

    // prefetch Cin as float4 (overlaps with acc->SMEM transpose + barrier)
    float4 cin4[4];
    #pragma unroll
    for (int kk = 0; kk < 4; kk++) {
        const int idx = kk * 256 + tid;
        const int m = idx >> 3, c4 = (idx & 7) * 4;
        cin4[kk] = *reinterpret_cast<const float4*>(&Cin[(mbase + m) * 2048 + hb + c4]);
    }

    #pragma unroll
    for (int mi = 0; mi < 4; mi++) {
        const int r0 = wm * 64 + mi * 16 + (lane >> 2);
        #pragma unroll
        for (int ni = 0; ni < 4; ni++) {
            const int c0 = wn * 32 + ni * 8 + (lane & 3) * 2;
            *reinterpret_cast<float2*>(&sC[r0 * 132 + c0]) =
                make_float2(acc[mi][ni][0], acc[mi][ni][1]);
            *reinterpret_cast<float2*>(&sC[(r0 + 8) * 132 + c0]) =
                make_float2(acc[mi][ni][2], acc[mi][ni][3]);
        }
    }
    __syncthreads();

    #pragma unroll
    for (int kk = 0; kk < 4; kk++) {
        const int idx = kk * 256 + tid;
        const int m = idx >> 3, c4 = (idx & 7) * 4;
        const float* row = &sC[m * 132 + c4];

        const float4 gf = *reinterpret_cast<const float4*>(row);
        const float4 gi = *reinterpret_cast<const float4*>(row + 32);
        const float4 gs = *reinterpret_cast<const float4*>(row + 64);
        const float4 gg = *reinterpret_cast<const float4*>(row + 96);
        const float4 bf = *reinterpret_cast<const float4*>(&s_bias[c4]);
        const float4 bi = *reinterpret_cast<const float4*>(&s_bias[32 + c4]);
        const float4 bs = *reinterpret_cast<const float4*>(&s_bias[64 + c4]);
        const float4 bo = *reinterpret_cast<const float4*>(&s_bias[96 + c4]);
        const float4 cc = cin4[kk];

        float4 hn, cn, oo;
        {
            const float f = sigf(gf.x + bf.x), i = sigf(gi.x + bi.x);
            const float s = tanhp(gs.x + bs.x), o = sigf(gg.x + bo.x);
            cn.x = f * cc.x + i * s; hn.x = o * tanhp(cn.x); oo.x = o;
        }
        {
            const float f = sigf(gf.y + bf.y), i = sigf(gi.y + bi.y);
            const float s = tanhp(gs.y + bs.y), o = sigf(gg.y + bo.y);
            cn.y = f * cc.y + i * s; hn.y = o * tanhp(cn.y); oo.y = o;
        }
        {
            const float f = sigf(gf.z + bf.z), i = sigf(gi.z + bi.z);
            const float s = tanhp(gs.z + bs.z), o = sigf(gg.z + bo.z);
            cn.z = f * cc.z + i * s; hn.z = o * tanhp(cn.z); oo.z = o;
        }
        {
            const float f = sigf(gf.w + bf.w), i = sigf(gi.w + bi.w);
            const float s = tanhp(gs.w + bs.w), o = sigf(gg.w + bo.w);
            cn.w = f * cc.w + i * s; hn.w = o * tanhp(cn.w); oo.w = o;
        }

        const size_t off = (mbase + m) * 2048 + hb + c4;
        *reinterpret_cast<float4*>(&Oh[off]) = hn;
        *reinterpret_cast<float4*>(&Oc[off]) = cn;
        *reinterpret_cast<float4*>(&Og[off]) = oo;
    }
}

// ============================================================================
// launch
// ============================================================================
extern "C" void kernel_launch(void* const* d_in, const int* in_sizes, int n_in,
                              void* d_out, int out_size)
{
    const float* x    = (const float*)d_in[0];
    const float* h    = (const float*)d_in[1];
    const float* c    = (const float*)d_in[2];
    /* d_in[3] = o, unused by the reference computation */
    const float* w_ih = (const float*)d_in[4];
    const float* w_hh = (const float*)d_in[5];
    const float* b    = (const float*)d_in[6];
    float* out = (float*)d_out;

    cudaFuncSetAttribute(lstm_gemm,
                         cudaFuncAttributeMaxDynamicSharedMemorySize, SMEM_ALLOC);

    cvt_pack<<<6144, 256>>>(x, h, w_ih, w_hh);

    float* out_h  = out;
    float* out_c  = out + (size_t)4096 * 2048;
    float* out_go = out + (size_t)2 * 4096 * 2048;
    lstm_gemm<<<2048, 256, SMEM_ALLOC>>>(b, c, out_h, out_c, out_go);
}